// round 2
// baseline (speedup 1.0000x reference)
#include <cuda_runtime.h>
#include <cstdint>

#define NN 50000
#define DD 128
#define EE 800000
#define LL 3
#define BN_EPS_F 1e-5f

// Scratch (no allocations allowed) — 3 x 25.6 MB
__device__ float g_agg[(size_t)NN * DD];
__device__ float g_h[(size_t)NN * DD];
__device__ float g_z[(size_t)NN * DD];
__device__ int   g_flag64;   // 1 if edge_index is genuinely int64, 0 if int32

// ---------------------------------------------------------------------------
// Detect edge_index dtype: read first 1024 entries as int64; all in [0,NN)
// => real int64. If the buffer is int32 data, the int64 view has a random
// nonzero hi-word almost surely => out of range.
// ---------------------------------------------------------------------------
__global__ void detect_kernel(const long long* __restrict__ ei)
{
    if (blockIdx.x == 0 && threadIdx.x == 0) {
        int ok = 1;
        for (int i = 0; i < 1024; i++) {
            long long v = ei[i];
            if (v < 0 || v >= NN) { ok = 0; break; }
        }
        g_flag64 = ok;
    }
}

// ---------------------------------------------------------------------------
// Edge scatter-add: one warp per edge. Each lane moves one float4 (128 floats
// per edge). Gather from h[src], vectorized RED.ADD.v4.f32 into agg[dst].
// h table = 25.6 MB -> L2-resident, so gathers are mostly L2 hits.
// ---------------------------------------------------------------------------
__global__ void __launch_bounds__(256) scatter_kernel(
    const float* __restrict__ h,
    const void* __restrict__ ei_raw,
    float* __restrict__ agg)
{
    unsigned gw = (blockIdx.x * blockDim.x + threadIdx.x) >> 5;
    if (gw >= EE) return;
    int lane = threadIdx.x & 31;

    int src, dst;
    if (g_flag64) {
        const long long* ei = (const long long*)ei_raw;
        src = (int)ei[gw];
        dst = (int)ei[(size_t)EE + gw];
    } else {
        const int* ei = (const int*)ei_raw;
        src = ei[gw];
        dst = ei[(size_t)EE + gw];
    }
    // safety clamp (defensive; indices are in-range by construction)
    if ((unsigned)src >= NN || (unsigned)dst >= NN) return;

    const float4 v = *reinterpret_cast<const float4*>(h + (size_t)src * DD + lane * 4);
    float* p = agg + (size_t)dst * DD + lane * 4;
    asm volatile("red.global.add.v4.f32 [%0], {%1,%2,%3,%4};"
                 :: "l"(p), "f"(v.x), "f"(v.y), "f"(v.z), "f"(v.w)
                 : "memory");
}

// ---------------------------------------------------------------------------
// Fused GEMM: out[n x 128] = A[n x 128] @ W[128 x 128] (+ epilogue)
//   MODE 1: A_eff = (1+eps[layer])*A + A2  (GIN combine), epilogue = BN + ReLU
//   MODE 0: epilogue = acc + bias, optional ReLU
// Block: 256 threads, tile 128x128, K chunked by 32, 8x8 accum per thread.
// ---------------------------------------------------------------------------
template <int MODE>
__global__ void __launch_bounds__(256) gemm128_kernel(
    const float* __restrict__ A,
    const float* __restrict__ A2,
    const float* __restrict__ eps, int layer,
    const float* __restrict__ W,
    const float* __restrict__ bias,
    const float* __restrict__ gamma, const float* __restrict__ beta,
    const float* __restrict__ mean, const float* __restrict__ var,
    float* __restrict__ out, int nrows, int doRelu)
{
    __shared__ float As[32][132];
    __shared__ float Bs[32][128];

    const int tid  = threadIdx.x;          // 0..255
    const int row0 = blockIdx.x * 128;
    const int tr   = (tid >> 4) * 8;       // thread row within tile
    const int tc   = (tid & 15) * 8;       // thread col within tile

    float ev = 0.0f;
    if (MODE == 1) ev = 1.0f + eps[layer];

    float acc[8][8];
#pragma unroll
    for (int m = 0; m < 8; m++)
#pragma unroll
        for (int n = 0; n < 8; n++) acc[m][n] = 0.0f;

#pragma unroll
    for (int kc = 0; kc < 4; ++kc) {
        // --- load A tile (128 rows x 32 k), transposed into As[k][row] ---
#pragma unroll
        for (int i = 0; i < 4; i++) {
            int q  = tid + i * 256;         // 0..1023 float4 slots
            int r  = q >> 3;                // row in tile
            int kq = (q & 7) << 2;          // k within chunk (step 4)
            int grow = row0 + r;
            float4 v = make_float4(0.f, 0.f, 0.f, 0.f);
            if (grow < nrows) {
                v = *reinterpret_cast<const float4*>(A + (size_t)grow * DD + kc * 32 + kq);
                if (MODE == 1) {
                    float4 w = *reinterpret_cast<const float4*>(A2 + (size_t)grow * DD + kc * 32 + kq);
                    v.x = ev * v.x + w.x;
                    v.y = ev * v.y + w.y;
                    v.z = ev * v.z + w.z;
                    v.w = ev * v.w + w.w;
                }
            }
            As[kq + 0][r] = v.x;
            As[kq + 1][r] = v.y;
            As[kq + 2][r] = v.z;
            As[kq + 3][r] = v.w;
        }
        // --- load B tile (32 k-rows x 128 cols) ---
#pragma unroll
        for (int i = 0; i < 4; i++) {
            int q  = tid + i * 256;         // 0..1023 float4 slots
            int r  = q >> 5;                // k-row (32 float4 per row)
            int cq = (q & 31) << 2;         // col
            float4 v = *reinterpret_cast<const float4*>(W + (size_t)(kc * 32 + r) * DD + cq);
            *reinterpret_cast<float4*>(&Bs[r][cq]) = v;
        }
        __syncthreads();

#pragma unroll
        for (int k = 0; k < 32; k++) {
            float ra[8], rb[8];
#pragma unroll
            for (int m = 0; m < 8; m++) ra[m] = As[k][tr + m];
#pragma unroll
            for (int n = 0; n < 8; n++) rb[n] = Bs[k][tc + n];
#pragma unroll
            for (int m = 0; m < 8; m++)
#pragma unroll
                for (int n = 0; n < 8; n++) acc[m][n] += ra[m] * rb[n];
        }
        __syncthreads();
    }

    // --- epilogue: per-column scale/shift ---
    float s[8], t[8];
#pragma unroll
    for (int n = 0; n < 8; n++) {
        int c = tc + n;
        if (MODE == 1) {
            float sc = gamma[c] * rsqrtf(var[c] + BN_EPS_F);
            s[n] = sc;
            t[n] = (bias[c] - mean[c]) * sc + beta[c];
        } else {
            s[n] = 1.0f;
            t[n] = bias[c];
        }
    }

#pragma unroll
    for (int m = 0; m < 8; m++) {
        int grow = row0 + tr + m;
        if (grow < nrows) {
#pragma unroll
            for (int n = 0; n < 8; n += 4) {
                float4 v;
                v.x = acc[m][n + 0] * s[n + 0] + t[n + 0];
                v.y = acc[m][n + 1] * s[n + 1] + t[n + 1];
                v.z = acc[m][n + 2] * s[n + 2] + t[n + 2];
                v.w = acc[m][n + 3] * s[n + 3] + t[n + 3];
                if (doRelu) {
                    v.x = fmaxf(v.x, 0.f);
                    v.y = fmaxf(v.y, 0.f);
                    v.z = fmaxf(v.z, 0.f);
                    v.w = fmaxf(v.w, 0.f);
                }
                *reinterpret_cast<float4*>(out + (size_t)grow * DD + tc + n) = v;
            }
        }
    }
}

// ---------------------------------------------------------------------------
// Launcher
// Inputs (metadata order): x, edge_index, W1, b1, gamma, beta, bn_mean,
//                          bn_var, W2, b2, eps
// ---------------------------------------------------------------------------
extern "C" void kernel_launch(void* const* d_in, const int* in_sizes, int n_in,
                              void* d_out, int out_size)
{
    const float* x    = (const float*)d_in[0];
    const void*  ei   = d_in[1];
    const float* W1   = (const float*)d_in[2];
    const float* b1   = (const float*)d_in[3];
    const float* gam  = (const float*)d_in[4];
    const float* bet  = (const float*)d_in[5];
    const float* bmu  = (const float*)d_in[6];
    const float* bva  = (const float*)d_in[7];
    const float* W2   = (const float*)d_in[8];
    const float* b2   = (const float*)d_in[9];
    const float* eps  = (const float*)d_in[10];
    float*       out  = (float*)d_out;

    float *agg, *hbuf, *zbuf;
    cudaGetSymbolAddress((void**)&agg,  g_agg);
    cudaGetSymbolAddress((void**)&hbuf, g_h);
    cudaGetSymbolAddress((void**)&zbuf, g_z);

    const size_t feat_bytes = (size_t)NN * DD * sizeof(float);
    const int scat_blocks = (EE * 32 + 255) / 256;       // one warp per edge
    const int gemm_blocks = (NN + 127) / 128;            // 391

    detect_kernel<<<1, 32>>>((const long long*)ei);

    const float* hin = x;
    for (int l = 0; l < LL; ++l) {
        float* hout = (l == LL - 1) ? out : hbuf;

        cudaMemsetAsync(agg, 0, feat_bytes, 0);
        scatter_kernel<<<scat_blocks, 256>>>(hin, ei, agg);

        // z = relu(BN(((1+eps)h + agg) @ W1 + b1))
        gemm128_kernel<1><<<gemm_blocks, 256>>>(
            hin, agg, eps, l,
            W1 + (size_t)l * DD * DD, b1 + (size_t)l * DD,
            gam + (size_t)l * DD, bet + (size_t)l * DD,
            bmu + (size_t)l * DD, bva + (size_t)l * DD,
            zbuf, NN, 1);

        // h = (z @ W2 + b2), relu except last layer
        gemm128_kernel<0><<<gemm_blocks, 256>>>(
            zbuf, nullptr, nullptr, 0,
            W2 + (size_t)l * DD * DD, b2 + (size_t)l * DD,
            nullptr, nullptr, nullptr, nullptr,
            hout, NN, (l < LL - 1) ? 1 : 0);

        hin = hout;
    }
}

// round 4
// speedup vs baseline: 2.3022x; 2.3022x over previous
#include <cuda_runtime.h>
#include <cuda_bf16.h>
#include <cstdint>

#define NN 50000
#define DD 128
#define EE 800000
#define LL 3
#define BN_EPS_F 1e-5f

// Scratch (no allocations allowed)
__device__ float g_agg[(size_t)NN * DD];
__device__ float g_h[(size_t)NN * DD];
__device__ int   g_flag64;

// ---------------------------------------------------------------------------
// smem layout: row-major bf16 tiles, 136 bf16 (272 B) row stride
// ---------------------------------------------------------------------------
#define ST_E    136
#define ROWB    272
#define TILEB   (128 * ROWB)      // 34816
#define OFF_AH  0
#define OFF_AL  (OFF_AH + TILEB)
#define OFF_W1H (OFF_AL + TILEB)
#define OFF_W1L (OFF_W1H + TILEB)
#define OFF_W2H (OFF_W1L + TILEB)
#define OFF_W2L (OFF_W2H + TILEB)
#define OFF_S   (OFF_W2L + TILEB)         // 512 B: BN scale
#define OFF_T   (OFF_S + 512)             // 512 B: BN shift (incl. b1)
#define OFF_B2  (OFF_T + 512)             // 512 B: b2
#define SMEM_TOTAL (OFF_B2 + 512)         // 210432 B

__device__ __forceinline__ uint32_t smem_u32(const void* p) {
    uint32_t a;
    asm("{ .reg .u64 t; cvta.to.shared.u64 t, %1; cvt.u32.u64 %0, t; }" : "=r"(a) : "l"(p));
    return a;
}
__device__ __forceinline__ void ldsm4(uint32_t r[4], uint32_t a) {
    asm volatile("ldmatrix.sync.aligned.m8n8.x4.shared.b16 {%0,%1,%2,%3}, [%4];"
                 : "=r"(r[0]), "=r"(r[1]), "=r"(r[2]), "=r"(r[3]) : "r"(a));
}
__device__ __forceinline__ void ldsm4t(uint32_t r[4], uint32_t a) {
    asm volatile("ldmatrix.sync.aligned.m8n8.x4.trans.shared.b16 {%0,%1,%2,%3}, [%4];"
                 : "=r"(r[0]), "=r"(r[1]), "=r"(r[2]), "=r"(r[3]) : "r"(a));
}
__device__ __forceinline__ void mma_bf16(float d[4], const uint32_t a[4], const uint32_t* b) {
    asm volatile("mma.sync.aligned.m16n8k16.row.col.f32.bf16.bf16.f32 "
                 "{%0,%1,%2,%3}, {%4,%5,%6,%7}, {%8,%9}, {%0,%1,%2,%3};"
                 : "+f"(d[0]), "+f"(d[1]), "+f"(d[2]), "+f"(d[3])
                 : "r"(a[0]), "r"(a[1]), "r"(a[2]), "r"(a[3]), "r"(b[0]), "r"(b[1]));
}
__device__ __forceinline__ uint32_t b2u(__nv_bfloat162 v) {
    return *reinterpret_cast<uint32_t*>(&v);
}
// split (x,y) into bf16-hi pair and bf16-lo (residual) pair
__device__ __forceinline__ void split_pair(float x, float y, uint32_t& hi, uint32_t& lo) {
    __nv_bfloat16 hx = __float2bfloat16(x);
    __nv_bfloat16 hy = __float2bfloat16(y);
    hi = b2u(__halves2bfloat162(hx, hy));
    lo = b2u(__floats2bfloat162_rn(x - __bfloat162float(hx), y - __bfloat162float(hy)));
}

// ---------------------------------------------------------------------------
// Fused GIN layer: out = [relu]( relu(BN(((1+eps)h + agg) @ W1 + b1)) @ W2 + b2 )
// 128-row tile per CTA; split-bf16 HMMA (3 passes) for both GEMMs.
// ---------------------------------------------------------------------------
template <int RELU2>
__global__ void __launch_bounds__(256, 1) fused_layer_kernel(
    const float* __restrict__ hin, const float* __restrict__ agg,
    const float* __restrict__ eps, int layer,
    const float* __restrict__ W1, const float* __restrict__ b1,
    const float* __restrict__ gamma, const float* __restrict__ beta,
    const float* __restrict__ mean, const float* __restrict__ var,
    const float* __restrict__ W2, const float* __restrict__ b2,
    float* __restrict__ out)
{
    extern __shared__ __align__(128) char smem[];
    const uint32_t sb = smem_u32(smem);
    const int tid = threadIdx.x, lane = tid & 31, wid = tid >> 5;
    const int row0 = blockIdx.x * 128;
    const int wm = wid & 3, wn = wid >> 2;         // 4 x 2 warp grid
    const int m0 = wm * 32, n0 = wn * 64;

    // ---- BN / bias precompute ----
    if (tid < 128) {
        float sc = gamma[tid] * rsqrtf(var[tid] + BN_EPS_F);
        *(float*)(smem + OFF_S + tid * 4) = sc;
        *(float*)(smem + OFF_T + tid * 4) = (b1[tid] - mean[tid]) * sc + beta[tid];
        *(float*)(smem + OFF_B2 + tid * 4) = b2[tid];
    }

    // ---- W1/W2 -> bf16 hi/lo smem tiles, native [k][n] layout (coalesced) ----
#pragma unroll
    for (int w = 0; w < 2; w++) {
        const float* Wsrc = w ? W2 : W1;
        const int ho = w ? OFF_W2H : OFF_W1H;
        const int lo = w ? OFF_W2L : OFF_W1L;
#pragma unroll
        for (int it = 0; it < 16; it++) {
            int q = tid + it * 256;                // 4096 float4 slots
            int k = q >> 5, c4 = (q & 31) << 2;
            float4 v = *(const float4*)(Wsrc + (size_t)k * DD + c4);
            uint2 hh, ll;
            split_pair(v.x, v.y, hh.x, ll.x);
            split_pair(v.z, v.w, hh.y, ll.y);
            uint32_t o = (uint32_t)k * ROWB + (uint32_t)c4 * 2;
            *(uint2*)(smem + ho + o) = hh;
            *(uint2*)(smem + lo + o) = ll;
        }
    }

    // ---- A tile: (1+eps)*h + agg -> bf16 hi/lo ----
    {
        const float ev = 1.0f + eps[layer];
#pragma unroll
        for (int it = 0; it < 16; it++) {
            int q = tid + it * 256;
            int m = q >> 5, c4 = (q & 31) << 2;
            int grow = row0 + m;
            float4 v = make_float4(0.f, 0.f, 0.f, 0.f);
            if (grow < NN) {
                v = *(const float4*)(hin + (size_t)grow * DD + c4);
                float4 a = *(const float4*)(agg + (size_t)grow * DD + c4);
                v.x = ev * v.x + a.x; v.y = ev * v.y + a.y;
                v.z = ev * v.z + a.z; v.w = ev * v.w + a.w;
            }
            uint2 hh, ll;
            split_pair(v.x, v.y, hh.x, ll.x);
            split_pair(v.z, v.w, hh.y, ll.y);
            uint32_t o = (uint32_t)m * ROWB + (uint32_t)c4 * 2;
            *(uint2*)(smem + OFF_AH + o) = hh;
            *(uint2*)(smem + OFF_AL + o) = ll;
        }
    }
    __syncthreads();

    // per-lane ldmatrix base offsets
    // A (non-trans): row = m0 + mt*16 + (lane&15), col = k0 + (lane>>4)*8
    const uint32_t aRowOff = (uint32_t)(m0 + (lane & 15)) * ROWB + (uint32_t)(lane >> 4) * 16;
    // B (trans, [k][n]): row = k0 + (lane&15), col = n0 + nt2*16 + (lane>>4)*8
    const uint32_t bRowOff = (uint32_t)(lane & 15) * ROWB + (uint32_t)(n0 + ((lane >> 4) << 3)) * 2;

    float d[2][8][4];

    // ===================== GEMM pass macro =====================
#define RUN_GEMM(AOFF_H, AOFF_L, WOFF_H, WOFF_L)                                \
    {                                                                           \
        _Pragma("unroll")                                                       \
        for (int mt = 0; mt < 2; mt++)                                          \
            _Pragma("unroll")                                                   \
            for (int nt = 0; nt < 8; nt++)                                      \
                _Pragma("unroll")                                               \
                for (int e = 0; e < 4; e++) d[mt][nt][e] = 0.f;                 \
        const uint32_t aB[3] = { sb + AOFF_H + aRowOff, sb + AOFF_H + aRowOff,  \
                                 sb + AOFF_L + aRowOff };                       \
        const uint32_t bB[3] = { sb + WOFF_H + bRowOff, sb + WOFF_L + bRowOff,  \
                                 sb + WOFF_H + bRowOff };                       \
        for (int p = 0; p < 3; p++) {                                           \
            _Pragma("unroll")                                                   \
            for (int kk = 0; kk < 8; kk++) {                                    \
                uint32_t afr[2][4], bfr[4][4];                                  \
                ldsm4(afr[0], aB[p] + kk * 32);                                 \
                ldsm4(afr[1], aB[p] + 16 * ROWB + kk * 32);                     \
                _Pragma("unroll")                                               \
                for (int j = 0; j < 4; j++)                                     \
                    ldsm4t(bfr[j], bB[p] + (uint32_t)kk * 16 * ROWB + j * 32);  \
                _Pragma("unroll")                                               \
                for (int mt = 0; mt < 2; mt++)                                  \
                    _Pragma("unroll")                                           \
                    for (int j = 0; j < 4; j++) {                               \
                        mma_bf16(d[mt][2 * j],     afr[mt], &bfr[j][0]);        \
                        mma_bf16(d[mt][2 * j + 1], afr[mt], &bfr[j][2]);        \
                    }                                                           \
            }                                                                   \
        }                                                                       \
    }

    // ---- GEMM1 ----
    RUN_GEMM(OFF_AH, OFF_AL, OFF_W1H, OFF_W1L);
    __syncthreads();   // all reads of As done before z overwrites it

    // ---- Epilogue 1: BN + ReLU -> z back into A tiles (bf16 hi/lo) ----
    {
        const int g = lane >> 2, tg = lane & 3;
#pragma unroll
        for (int mt = 0; mt < 2; mt++) {
#pragma unroll
            for (int nt = 0; nt < 8; nt++) {
                int c = n0 + nt * 8 + tg * 2;
                float s0 = *(const float*)(smem + OFF_S + c * 4);
                float s1 = *(const float*)(smem + OFF_S + c * 4 + 4);
                float t0 = *(const float*)(smem + OFF_T + c * 4);
                float t1 = *(const float*)(smem + OFF_T + c * 4 + 4);
                int r0 = m0 + mt * 16 + g, r1 = r0 + 8;
                float z00 = fmaxf(d[mt][nt][0] * s0 + t0, 0.f);
                float z01 = fmaxf(d[mt][nt][1] * s1 + t1, 0.f);
                float z10 = fmaxf(d[mt][nt][2] * s0 + t0, 0.f);
                float z11 = fmaxf(d[mt][nt][3] * s1 + t1, 0.f);
                uint32_t hi, lo;
                uint32_t o0 = (uint32_t)r0 * ROWB + (uint32_t)c * 2;
                uint32_t o1 = (uint32_t)r1 * ROWB + (uint32_t)c * 2;
                split_pair(z00, z01, hi, lo);
                *(uint32_t*)(smem + OFF_AH + o0) = hi;
                *(uint32_t*)(smem + OFF_AL + o0) = lo;
                split_pair(z10, z11, hi, lo);
                *(uint32_t*)(smem + OFF_AH + o1) = hi;
                *(uint32_t*)(smem + OFF_AL + o1) = lo;
            }
        }
    }
    __syncthreads();

    // ---- GEMM2 ----
    RUN_GEMM(OFF_AH, OFF_AL, OFF_W2H, OFF_W2L);

    // ---- Epilogue 2: + b2, optional ReLU, store to gmem ----
    {
        const int g = lane >> 2, tg = lane & 3;
#pragma unroll
        for (int mt = 0; mt < 2; mt++) {
            int r0 = row0 + m0 + mt * 16 + g;
            int r1 = r0 + 8;
#pragma unroll
            for (int nt = 0; nt < 8; nt++) {
                int c = n0 + nt * 8 + tg * 2;
                float bb0 = *(const float*)(smem + OFF_B2 + c * 4);
                float bb1 = *(const float*)(smem + OFF_B2 + c * 4 + 4);
                float2 v0 = make_float2(d[mt][nt][0] + bb0, d[mt][nt][1] + bb1);
                float2 v1 = make_float2(d[mt][nt][2] + bb0, d[mt][nt][3] + bb1);
                if (RELU2) {
                    v0.x = fmaxf(v0.x, 0.f); v0.y = fmaxf(v0.y, 0.f);
                    v1.x = fmaxf(v1.x, 0.f); v1.y = fmaxf(v1.y, 0.f);
                }
                if (r0 < NN) *(float2*)(out + (size_t)r0 * DD + c) = v0;
                if (r1 < NN) *(float2*)(out + (size_t)r1 * DD + c) = v1;
            }
        }
    }
#undef RUN_GEMM
}

// ---------------------------------------------------------------------------
// edge_index dtype detect (int64 vs int32) + scatter-add
// ---------------------------------------------------------------------------
__global__ void detect_kernel(const long long* __restrict__ ei)
{
    if (blockIdx.x == 0 && threadIdx.x == 0) {
        int ok = 1;
        for (int i = 0; i < 1024; i++) {
            long long v = ei[i];
            if (v < 0 || v >= NN) { ok = 0; break; }
        }
        g_flag64 = ok;
    }
}

__global__ void __launch_bounds__(256) scatter_kernel(
    const float* __restrict__ h,
    const void* __restrict__ ei_raw,
    float* __restrict__ agg)
{
    unsigned gw = (blockIdx.x * blockDim.x + threadIdx.x) >> 5;
    if (gw >= EE) return;
    int lane = threadIdx.x & 31;

    int src, dst;
    if (g_flag64) {
        const long long* ei = (const long long*)ei_raw;
        src = (int)ei[gw];
        dst = (int)ei[(size_t)EE + gw];
    } else {
        const int* ei = (const int*)ei_raw;
        src = ei[gw];
        dst = ei[(size_t)EE + gw];
    }
    if ((unsigned)src >= NN || (unsigned)dst >= NN) return;

    const float4 v = *reinterpret_cast<const float4*>(h + (size_t)src * DD + lane * 4);
    float* p = agg + (size_t)dst * DD + lane * 4;
    asm volatile("red.global.add.v4.f32 [%0], {%1,%2,%3,%4};"
                 :: "l"(p), "f"(v.x), "f"(v.y), "f"(v.z), "f"(v.w)
                 : "memory");
}

// ---------------------------------------------------------------------------
// Launcher
// ---------------------------------------------------------------------------
extern "C" void kernel_launch(void* const* d_in, const int* in_sizes, int n_in,
                              void* d_out, int out_size)
{
    const float* x   = (const float*)d_in[0];
    const void*  ei  = d_in[1];
    const float* W1  = (const float*)d_in[2];
    const float* b1  = (const float*)d_in[3];
    const float* gam = (const float*)d_in[4];
    const float* bet = (const float*)d_in[5];
    const float* bmu = (const float*)d_in[6];
    const float* bva = (const float*)d_in[7];
    const float* W2  = (const float*)d_in[8];
    const float* b2  = (const float*)d_in[9];
    const float* eps = (const float*)d_in[10];
    float*       out = (float*)d_out;

    float *agg, *hbuf;
    cudaGetSymbolAddress((void**)&agg,  g_agg);
    cudaGetSymbolAddress((void**)&hbuf, g_h);

    cudaFuncSetAttribute(fused_layer_kernel<1>, cudaFuncAttributeMaxDynamicSharedMemorySize, SMEM_TOTAL);
    cudaFuncSetAttribute(fused_layer_kernel<0>, cudaFuncAttributeMaxDynamicSharedMemorySize, SMEM_TOTAL);

    const size_t feat_bytes = (size_t)NN * DD * sizeof(float);
    const int scat_blocks = (EE * 32 + 255) / 256;
    const int gemm_blocks = (NN + 127) / 128;   // 391

    detect_kernel<<<1, 32>>>((const long long*)ei);

    const float* hin = x;
    for (int l = 0; l < LL; ++l) {
        float* hout = (l == LL - 1) ? out : hbuf;

        cudaMemsetAsync(agg, 0, feat_bytes, 0);
        scatter_kernel<<<scat_blocks, 256>>>(hin, ei, agg);

        if (l < LL - 1) {
            fused_layer_kernel<1><<<gemm_blocks, 256, SMEM_TOTAL>>>(
                hin, agg, eps, l,
                W1 + (size_t)l * DD * DD, b1 + (size_t)l * DD,
                gam + (size_t)l * DD, bet + (size_t)l * DD,
                bmu + (size_t)l * DD, bva + (size_t)l * DD,
                W2 + (size_t)l * DD * DD, b2 + (size_t)l * DD,
                hout);
        } else {
            fused_layer_kernel<0><<<gemm_blocks, 256, SMEM_TOTAL>>>(
                hin, agg, eps, l,
                W1 + (size_t)l * DD * DD, b1 + (size_t)l * DD,
                gam + (size_t)l * DD, bet + (size_t)l * DD,
                bmu + (size_t)l * DD, bva + (size_t)l * DD,
                W2 + (size_t)l * DD * DD, b2 + (size_t)l * DD,
                hout);
        }
        hin = hout;
    }
}